// round 11
// baseline (speedup 1.0000x reference)
#include <cuda_runtime.h>

// Problem constants
#define BB      16
#define TT      1024
#define NK      1024
#define DD      256
#define WIN     64
#define TILE_T  32

// Shared-memory layout (floats). 260-float row stride => 4-bank shift per row
// (conflict-free 8-row strided LDS.128). Q is NOT staged: QK reads Q via LDG
// (4 unique 16B addresses per warp -> 64B dedup'd), freeing 33KB of smem so
// THREE CTAs fit per SM (3 x 75264B + overhead <= 233472B).
#define KS_STRIDE   260
#define PS_STRIDE   68

#define KS_OFF      0
#define PS_OFF      (WIN * KS_STRIDE)                    // 16640
#define SMEM_FLOATS (PS_OFF + TILE_T * PS_STRIDE)        // 18816 floats
#define SMEM_BYTES  (SMEM_FLOATS * 4)                    // 75264 B -> 3 CTAs/SM

// Output layout: R (B,T,512) | alignments (B,N,T) | max_attentions (B,T)
#define R_ELEMS   ((size_t)BB * TT * (2 * DD))           // 8,388,608
#define AL_ELEMS  ((size_t)BB * NK * TT)                 // 16,777,216

typedef unsigned long long u64;
typedef unsigned int       u32;

union UF2 { u64 u; float2 f; };

// Packed fp32x2 FMA (Blackwell FFMA2) — exact fp32, 2x FFMA throughput.
__device__ __forceinline__ u64 fma2(u64 a, u64 b, u64 c) {
    u64 d;
    asm("fma.rn.f32x2 %0, %1, %2, %3;" : "=l"(d) : "l"(a), "l"(b), "l"(c));
    return d;
}

// 16-byte async global->shared copy (LDGSTS).
__device__ __forceinline__ void cp_async16(u32 smem_addr, const void* gptr) {
    asm volatile("cp.async.cg.shared.global [%0], [%1], 16;"
                 :: "r"(smem_addr), "l"(gptr));
}
__device__ __forceinline__ void cp_async_commit() {
    asm volatile("cp.async.commit_group;");
}
__device__ __forceinline__ void cp_async_wait_all() {
    asm volatile("cp.async.wait_group 0;");
}

__global__ __launch_bounds__(256, 3)
void attn_win_kernel(const float* __restrict__ Q,
                     const float* __restrict__ K,
                     const float* __restrict__ V,
                     const int*   __restrict__ prev_words,  // raw words of prev_max_attentions
                     float* __restrict__ out)
{
    extern __shared__ float smem[];
    float* Ks = smem + KS_OFF;   // K window during QK, then reused for V window
    float* Ps = smem + PS_OFF;

    const int tid = threadIdx.x;
    const int b   = blockIdx.y;
    const int t0  = blockIdx.x * TILE_T;

    // dtype sniff: int64 (little-endian, values < 2^31) has zero high words.
    int odd_or = prev_words[1] | prev_words[3] | prev_words[5] | prev_words[7] |
                 prev_words[9] | prev_words[11] | prev_words[13] | prev_words[15];
    const int prev = (odd_or == 0) ? prev_words[2 * b] : prev_words[b];

    float* Rout = out;                       // (B,T,512)
    float* Aout = out + R_ELEMS;             // (B,N,T), zero-filled below
    float* Mout = Aout + AL_ELEMS;           // (B,T)

    // ---------------- K window -> smem via cp.async (starts first) -----------
    {
        const char* Kg = (const char*)(K + ((size_t)b * NK + prev) * DD);
        #pragma unroll
        for (int it = 0; it < (WIN * DD / 4) / 256; ++it) {      // 16 iters
            int idx = tid + it * 256;
            int j   = idx >> 6;          // 0..63
            int d4  = idx & 63;
            u32 dst = (u32)__cvta_generic_to_shared(Ks + j * KS_STRIDE + d4 * 4);
            cp_async16(dst, Kg + (size_t)(j * 64 + d4) * 16);
        }
        cp_async_commit();
    }
    // ---------------- Q tile -> R[:, :, 256:512] (streamed, no smem) ---------
    {
        const float4* Qg = (const float4*)(Q + ((size_t)b * TT + t0) * DD);
        #pragma unroll
        for (int it = 0; it < (TILE_T * DD / 4) / 256; ++it) {   // 8 iters
            int idx = tid + it * 256;
            int t   = idx >> 6;          // 0..31
            int d4  = idx & 63;          // 0..63 (float4 index)
            float4 q4 = __ldg(&Qg[t * 64 + d4]);
            __stcs((float4*)(Rout + ((size_t)b * TT + t0 + t) * (2 * DD) + DD + d4 * 4), q4);
        }
    }
    cp_async_wait_all();
    __syncthreads();

    // =================== WARP-SPECIALIZED PHASE ==============================
    if (tid < 128) {
        // ------------- QK^T on warps 0-3: thread tile 4 t-rows x 4 j-cols ----
        // j = jh*32 + jg + 8*jj. K from smem (8 unique rows/warp, 4-bank shift
        // -> conflict-free). Q via LDG.128: 4 unique addresses per warp
        // (8-lane dedup), L2-resident. 4 LDS + 4 LDG feed 32 FFMA2 per iter.
        const int jg = tid & 7;
        const int tg = (tid >> 3) & 7;              // rows 4*tg .. 4*tg+3
        const int jh = tid >> 6;                    // j half: 0 or 1
        const ulonglong2* qg =
            (const ulonglong2*)(Q + ((size_t)b * TT + t0 + tg * 4) * DD);
        const float* kb = Ks + (size_t)(jh * 32 + jg) * KS_STRIDE;
        const int QROW = DD / 4;                    // Q row step in ulonglong2

        u64 acc[4][4];
        #pragma unroll
        for (int i = 0; i < 4; ++i)
            #pragma unroll
            for (int c = 0; c < 4; ++c) acc[i][c] = 0ull;

        #pragma unroll 2
        for (int d4 = 0; d4 < DD / 4; ++d4) {
            ulonglong2 k0 = *(const ulonglong2*)(kb + 0 * 8 * KS_STRIDE + d4 * 4);
            ulonglong2 k1 = *(const ulonglong2*)(kb + 1 * 8 * KS_STRIDE + d4 * 4);
            ulonglong2 k2 = *(const ulonglong2*)(kb + 2 * 8 * KS_STRIDE + d4 * 4);
            ulonglong2 k3 = *(const ulonglong2*)(kb + 3 * 8 * KS_STRIDE + d4 * 4);
            #pragma unroll
            for (int i = 0; i < 4; ++i) {
                ulonglong2 q = __ldg(&qg[i * QROW + d4]);
                acc[i][0] = fma2(q.x, k0.x, acc[i][0]);
                acc[i][0] = fma2(q.y, k0.y, acc[i][0]);
                acc[i][1] = fma2(q.x, k1.x, acc[i][1]);
                acc[i][1] = fma2(q.y, k1.y, acc[i][1]);
                acc[i][2] = fma2(q.x, k2.x, acc[i][2]);
                acc[i][2] = fma2(q.y, k2.y, acc[i][2]);
                acc[i][3] = fma2(q.x, k3.x, acc[i][3]);
                acc[i][3] = fma2(q.y, k3.y, acc[i][3]);
            }
        }
        #pragma unroll
        for (int i = 0; i < 4; ++i)
            #pragma unroll
            for (int c = 0; c < 4; ++c) {
                UF2 u; u.u = acc[i][c];
                Ps[(tg * 4 + i) * PS_STRIDE + jh * 32 + jg + 8 * c] =
                    (u.f.x + u.f.y) * 0.0625f;      // * rsqrt(256)
            }
    } else {
        // ------------- zero-fill non-window rows of alignments (warps 4-7) ---
        // Pure STG to global: overlaps fully with the QK compute above.
        const int t2   = tid - 128;
        const int rown = t2 >> 3;           // 0..15
        const int c4   = t2 & 7;            // float4 col of the 32 t-cols
        float* base = Aout + (size_t)b * NK * TT + t0 + 4 * c4;
        const float4 z = make_float4(0.f, 0.f, 0.f, 0.f);
        #pragma unroll 4
        for (int pass = 0; pass < NK / 16; ++pass) {
            int n = pass * 16 + rown;
            if ((unsigned)(n - prev) >= WIN)
                __stcs((float4*)(base + (size_t)n * TT), z);
        }
    }
    __syncthreads();   // Ks (K data) dead; Ps scores complete; zero-fill issued

    // ---------------- V window -> smem (reusing Ks) via cp.async -------------
    {
        const char* Vg = (const char*)(V + ((size_t)b * NK + prev) * DD);
        #pragma unroll
        for (int it = 0; it < (WIN * DD / 4) / 256; ++it) {      // 16 iters
            int idx = tid + it * 256;
            int j   = idx >> 6;          // 0..63
            int d4  = idx & 63;
            u32 dst = (u32)__cvta_generic_to_shared(Ks + j * KS_STRIDE + d4 * 4);
            cp_async16(dst, Vg + (size_t)(j * 64 + d4) * 16);
        }
        cp_async_commit();
    }

    // ---------------- softmax over 64 window cols + argmax -------------------
    {
        const int lane = tid & 31;
        const int w    = tid >> 5;                 // 8 warps x 4 rows
        #pragma unroll
        for (int rr = 0; rr < TILE_T / 8; ++rr) {
            int r = w * (TILE_T / 8) + rr;
            float v0 = Ps[r * PS_STRIDE + lane];
            float v1 = Ps[r * PS_STRIDE + lane + 32];
            float bv; int bi;
            if (v0 >= v1) { bv = v0; bi = lane; } else { bv = v1; bi = lane + 32; }
            #pragma unroll
            for (int off = 16; off > 0; off >>= 1) {
                float ov = __shfl_xor_sync(0xffffffffu, bv, off);
                int   oi = __shfl_xor_sync(0xffffffffu, bi, off);
                if (ov > bv || (ov == bv && oi < bi)) { bv = ov; bi = oi; }
            }
            float e0 = __expf(v0 - bv);
            float e1 = __expf(v1 - bv);
            float s = e0 + e1;
            #pragma unroll
            for (int off = 16; off > 0; off >>= 1)
                s += __shfl_xor_sync(0xffffffffu, s, off);
            float inv = 1.0f / s;
            Ps[r * PS_STRIDE + lane]      = e0 * inv;
            Ps[r * PS_STRIDE + lane + 32] = e1 * inv;
            if (lane == 0)
                Mout[(size_t)b * TT + t0 + r] = (float)(prev + bi);
        }
    }
    cp_async_wait_all();
    __syncthreads();   // probs + V-in-smem visible to all

    // ---------------- scatter probs into window rows of alignments -----------
    {
        const int rown = tid >> 3;          // 0..31
        const int c4   = tid & 7;
        float* base = Aout + (size_t)b * NK * TT + t0 + 4 * c4;
        #pragma unroll
        for (int pass = 0; pass < 2; ++pass) {
            int j = pass * 32 + rown;       // 0..63 window col
            int t = 4 * c4;
            float4 v;
            v.x = Ps[(t + 0) * PS_STRIDE + j];
            v.y = Ps[(t + 1) * PS_STRIDE + j];
            v.z = Ps[(t + 2) * PS_STRIDE + j];
            v.w = Ps[(t + 3) * PS_STRIDE + j];
            __stcs((float4*)(base + (size_t)(prev + j) * TT), v);
        }
    }

    // ---------------- P @ V_window -> R[:, :, 0:256] --------------------------
    // V in smem; thread owns 8 t-rows and one float4 d-column.
    {
        const int d8 = tid & 63;                   // float4 index 0..63
        const int tg = tid >> 6;                   // 0..3 -> rows 8*tg..+7
        u64 acc[8][2];
        #pragma unroll
        for (int r = 0; r < 8; ++r) { acc[r][0] = 0ull; acc[r][1] = 0ull; }

        #pragma unroll 2
        for (int j4 = 0; j4 < WIN / 4; ++j4) {
            ulonglong2 vv[4];
            #pragma unroll
            for (int jj = 0; jj < 4; ++jj)
                vv[jj] = *(const ulonglong2*)(Ks + (size_t)(j4 * 4 + jj) * KS_STRIDE + d8 * 4);
            #pragma unroll
            for (int r = 0; r < 8; ++r) {
                float4 p4 = *(const float4*)(Ps + (tg * 8 + r) * PS_STRIDE + j4 * 4);
                UF2 pp;
                pp.f = make_float2(p4.x, p4.x);
                acc[r][0] = fma2(pp.u, vv[0].x, acc[r][0]);
                acc[r][1] = fma2(pp.u, vv[0].y, acc[r][1]);
                pp.f = make_float2(p4.y, p4.y);
                acc[r][0] = fma2(pp.u, vv[1].x, acc[r][0]);
                acc[r][1] = fma2(pp.u, vv[1].y, acc[r][1]);
                pp.f = make_float2(p4.z, p4.z);
                acc[r][0] = fma2(pp.u, vv[2].x, acc[r][0]);
                acc[r][1] = fma2(pp.u, vv[2].y, acc[r][1]);
                pp.f = make_float2(p4.w, p4.w);
                acc[r][0] = fma2(pp.u, vv[3].x, acc[r][0]);
                acc[r][1] = fma2(pp.u, vv[3].y, acc[r][1]);
            }
        }
        #pragma unroll
        for (int r = 0; r < 8; ++r) {
            float* dst = Rout + ((size_t)b * TT + t0 + tg * 8 + r) * (2 * DD) + 4 * d8;
            float4 o;
            o.x = ((UF2*)&acc[r][0])->f.x;  o.y = ((UF2*)&acc[r][0])->f.y;
            o.z = ((UF2*)&acc[r][1])->f.x;  o.w = ((UF2*)&acc[r][1])->f.y;
            __stcs((float4*)dst, o);
        }
    }
}

extern "C" void kernel_launch(void* const* d_in, const int* in_sizes, int n_in,
                              void* d_out, int out_size)
{
    const float* Q  = (const float*)d_in[0];
    const float* K  = (const float*)d_in[1];
    const float* V  = (const float*)d_in[2];
    const int* prevw = (const int*)d_in[3];   // int64 or int32, sniffed in-kernel
    float* out = (float*)d_out;

    cudaFuncSetAttribute(attn_win_kernel,
                         cudaFuncAttributeMaxDynamicSharedMemorySize, SMEM_BYTES);

    dim3 grid(TT / TILE_T, BB);
    attn_win_kernel<<<grid, 256, SMEM_BYTES, 0>>>(Q, K, V, prevw, out);
}

// round 12
// speedup vs baseline: 1.4126x; 1.4126x over previous
#include <cuda_runtime.h>

// Problem constants
#define BB      16
#define TT      1024
#define NK      1024
#define DD      256
#define WIN     64
#define TILE_T  32

// Shared-memory layout (floats). 260-float row stride => 4-bank shift per row.
#define QS_STRIDE   260
#define KS_STRIDE   260
#define PS_STRIDE   68

#define QS_OFF      0
#define KS_OFF      (TILE_T * QS_STRIDE)                 // 8320
#define PS_OFF      (KS_OFF + WIN * KS_STRIDE)           // 24960
#define SMEM_FLOATS (PS_OFF + TILE_T * PS_STRIDE)        // 27136 floats
#define SMEM_BYTES  (SMEM_FLOATS * 4)                    // 108544 B -> 2 CTAs/SM

// Output layout: R (B,T,512) | alignments (B,N,T) | max_attentions (B,T)
#define R_ELEMS   ((size_t)BB * TT * (2 * DD))           // 8,388,608
#define AL_ELEMS  ((size_t)BB * NK * TT)                 // 16,777,216

typedef unsigned long long u64;
typedef unsigned int       u32;

union UF2 { u64 u; float2 f; };

// Packed fp32x2 FMA (Blackwell FFMA2) — exact fp32, 2x FFMA throughput.
__device__ __forceinline__ u64 fma2(u64 a, u64 b, u64 c) {
    u64 d;
    asm("fma.rn.f32x2 %0, %1, %2, %3;" : "=l"(d) : "l"(a), "l"(b), "l"(c));
    return d;
}

// 16-byte async global->shared copy (LDGSTS).
__device__ __forceinline__ void cp_async16(u32 smem_addr, const void* gptr) {
    asm volatile("cp.async.cg.shared.global [%0], [%1], 16;"
                 :: "r"(smem_addr), "l"(gptr));
}
__device__ __forceinline__ void cp_async_commit() {
    asm volatile("cp.async.commit_group;");
}
__device__ __forceinline__ void cp_async_wait_all() {
    asm volatile("cp.async.wait_group 0;");
}

__global__ __launch_bounds__(256, 2)
void attn_win_kernel(const float* __restrict__ Q,
                     const float* __restrict__ K,
                     const float* __restrict__ V,
                     const int*   __restrict__ prev_words,  // raw words of prev_max_attentions
                     float* __restrict__ out)
{
    extern __shared__ float smem[];
    float* Qs = smem + QS_OFF;
    float* Ks = smem + KS_OFF;   // K window during QK, then reused for V window
    float* Ps = smem + PS_OFF;

    const int tid = threadIdx.x;
    const int b   = blockIdx.y;
    const int t0  = blockIdx.x * TILE_T;

    // dtype sniff: int64 (little-endian, values < 2^31) has zero high words.
    int odd_or = prev_words[1] | prev_words[3] | prev_words[5] | prev_words[7] |
                 prev_words[9] | prev_words[11] | prev_words[13] | prev_words[15];
    const int prev = (odd_or == 0) ? prev_words[2 * b] : prev_words[b];

    float* Rout = out;                       // (B,T,512)
    float* Aout = out + R_ELEMS;             // (B,N,T), zero-filled below
    float* Mout = Aout + AL_ELEMS;           // (B,T)

    // ---------------- K window -> smem via cp.async (starts first) -----------
    {
        const char* Kg = (const char*)(K + ((size_t)b * NK + prev) * DD);
        #pragma unroll
        for (int it = 0; it < (WIN * DD / 4) / 256; ++it) {      // 16 iters
            int idx = tid + it * 256;
            int j   = idx >> 6;          // 0..63
            int d4  = idx & 63;
            u32 dst = (u32)__cvta_generic_to_shared(Ks + j * KS_STRIDE + d4 * 4);
            cp_async16(dst, Kg + (size_t)(j * 64 + d4) * 16);
        }
        cp_async_commit();
    }
    // ---------------- Q tile -> smem only (R copy deferred to QK phase) ------
    {
        const float4* Qg = (const float4*)(Q + ((size_t)b * TT + t0) * DD);
        #pragma unroll
        for (int it = 0; it < (TILE_T * DD / 4) / 256; ++it) {   // 8 iters
            int idx = tid + it * 256;
            int t   = idx >> 6;          // 0..31
            int d4  = idx & 63;          // 0..63 (float4 index)
            *(float4*)(Qs + t * QS_STRIDE + d4 * 4) = __ldg(&Qg[t * 64 + d4]);
        }
    }
    cp_async_wait_all();
    __syncthreads();

    // =================== WARP-SPECIALIZED PHASE 1 ============================
    if (tid < 128) {
        // ------------- QK^T on warps 0-3: thread tile 4 t-rows x 4 j-cols ----
        // j = jh*32 + jg + 8*jj. K loads: 8 unique rows/warp (4-bank shift ->
        // conflict-free). 8 LDS.128 feed 32 FFMA2 per iter.
        const int jg = tid & 7;
        const int tg = (tid >> 3) & 7;              // rows 4*tg .. 4*tg+3
        const int jh = tid >> 6;                    // j half: 0 or 1
        const float* qb = Qs + (size_t)(tg * 4) * QS_STRIDE;
        const float* kb = Ks + (size_t)(jh * 32 + jg) * KS_STRIDE;

        u64 acc[4][4];
        #pragma unroll
        for (int i = 0; i < 4; ++i)
            #pragma unroll
            for (int c = 0; c < 4; ++c) acc[i][c] = 0ull;

        #pragma unroll 2
        for (int d4 = 0; d4 < DD / 4; ++d4) {
            ulonglong2 k0 = *(const ulonglong2*)(kb + 0 * 8 * KS_STRIDE + d4 * 4);
            ulonglong2 k1 = *(const ulonglong2*)(kb + 1 * 8 * KS_STRIDE + d4 * 4);
            ulonglong2 k2 = *(const ulonglong2*)(kb + 2 * 8 * KS_STRIDE + d4 * 4);
            ulonglong2 k3 = *(const ulonglong2*)(kb + 3 * 8 * KS_STRIDE + d4 * 4);
            #pragma unroll
            for (int i = 0; i < 4; ++i) {
                ulonglong2 q = *(const ulonglong2*)(qb + (size_t)i * QS_STRIDE + d4 * 4);
                acc[i][0] = fma2(q.x, k0.x, acc[i][0]);
                acc[i][0] = fma2(q.y, k0.y, acc[i][0]);
                acc[i][1] = fma2(q.x, k1.x, acc[i][1]);
                acc[i][1] = fma2(q.y, k1.y, acc[i][1]);
                acc[i][2] = fma2(q.x, k2.x, acc[i][2]);
                acc[i][2] = fma2(q.y, k2.y, acc[i][2]);
                acc[i][3] = fma2(q.x, k3.x, acc[i][3]);
                acc[i][3] = fma2(q.y, k3.y, acc[i][3]);
            }
        }
        #pragma unroll
        for (int i = 0; i < 4; ++i)
            #pragma unroll
            for (int c = 0; c < 4; ++c) {
                UF2 u; u.u = acc[i][c];
                Ps[(tg * 4 + i) * PS_STRIDE + jh * 32 + jg + 8 * c] =
                    (u.f.x + u.f.y) * 0.0625f;      // * rsqrt(256)
            }
    } else {
        const int t2 = tid - 128;
        // ------------- Q -> R[:, :, 256:512] copy (warps 4-7; Q is L2-hot) ---
        {
            const float4* Qg = (const float4*)(Q + ((size_t)b * TT + t0) * DD);
            #pragma unroll
            for (int it = 0; it < (TILE_T * DD / 4) / 128; ++it) {   // 16 iters
                int idx = t2 + it * 128;
                int t   = idx >> 6;
                int d4  = idx & 63;
                __stcs((float4*)(Rout + ((size_t)b * TT + t0 + t) * (2 * DD) + DD + d4 * 4),
                       __ldg(&Qg[t * 64 + d4]));
            }
        }
        // ------------- zero-fill non-window rows of alignments ---------------
        {
            const int rown = t2 >> 3;           // 0..15
            const int c4   = t2 & 7;            // float4 col of the 32 t-cols
            float* base = Aout + (size_t)b * NK * TT + t0 + 4 * c4;
            const float4 z = make_float4(0.f, 0.f, 0.f, 0.f);
            #pragma unroll 4
            for (int pass = 0; pass < NK / 16; ++pass) {
                int n = pass * 16 + rown;
                if ((unsigned)(n - prev) >= WIN)
                    __stcs((float4*)(base + (size_t)n * TT), z);
            }
        }
    }
    __syncthreads();   // Ks (K data) dead; Ps scores complete

    // ---------------- V window -> smem (reusing Ks) via cp.async -------------
    {
        const char* Vg = (const char*)(V + ((size_t)b * NK + prev) * DD);
        #pragma unroll
        for (int it = 0; it < (WIN * DD / 4) / 256; ++it) {      // 16 iters
            int idx = tid + it * 256;
            int j   = idx >> 6;          // 0..63
            int d4  = idx & 63;
            u32 dst = (u32)__cvta_generic_to_shared(Ks + j * KS_STRIDE + d4 * 4);
            cp_async16(dst, Vg + (size_t)(j * 64 + d4) * 16);
        }
        cp_async_commit();
    }

    // ---------------- softmax over 64 window cols + argmax -------------------
    {
        const int lane = tid & 31;
        const int w    = tid >> 5;                 // 8 warps x 4 rows
        #pragma unroll
        for (int rr = 0; rr < TILE_T / 8; ++rr) {
            int r = w * (TILE_T / 8) + rr;
            float v0 = Ps[r * PS_STRIDE + lane];
            float v1 = Ps[r * PS_STRIDE + lane + 32];
            float bv; int bi;
            if (v0 >= v1) { bv = v0; bi = lane; } else { bv = v1; bi = lane + 32; }
            #pragma unroll
            for (int off = 16; off > 0; off >>= 1) {
                float ov = __shfl_xor_sync(0xffffffffu, bv, off);
                int   oi = __shfl_xor_sync(0xffffffffu, bi, off);
                if (ov > bv || (ov == bv && oi < bi)) { bv = ov; bi = oi; }
            }
            float e0 = __expf(v0 - bv);
            float e1 = __expf(v1 - bv);
            float s = e0 + e1;
            #pragma unroll
            for (int off = 16; off > 0; off >>= 1)
                s += __shfl_xor_sync(0xffffffffu, s, off);
            float inv = 1.0f / s;
            Ps[r * PS_STRIDE + lane]      = e0 * inv;
            Ps[r * PS_STRIDE + lane + 32] = e1 * inv;
            if (lane == 0)
                Mout[(size_t)b * TT + t0 + r] = (float)(prev + bi);
        }
    }
    cp_async_wait_all();
    __syncthreads();   // probs + V-in-smem visible to all

    // =================== WARP-SPECIALIZED PHASE 2 ============================
    if (tid < 128) {
        // ------------- P @ V_window -> R[:, :, 0:256] (warps 0-3) ------------
        // Thread owns 16 t-rows x one float4 d-col: V re-read redundancy 2x.
        const int d8 = tid & 63;                   // float4 index 0..63
        const int tg = tid >> 6;                   // 0..1 -> rows 16*tg..+15
        u64 acc[16][2];
        #pragma unroll
        for (int r = 0; r < 16; ++r) { acc[r][0] = 0ull; acc[r][1] = 0ull; }

        #pragma unroll 1
        for (int j4 = 0; j4 < WIN / 4; ++j4) {
            ulonglong2 vv[4];
            #pragma unroll
            for (int jj = 0; jj < 4; ++jj)
                vv[jj] = *(const ulonglong2*)(Ks + (size_t)(j4 * 4 + jj) * KS_STRIDE + d8 * 4);
            #pragma unroll
            for (int r = 0; r < 16; ++r) {
                float4 p4 = *(const float4*)(Ps + (tg * 16 + r) * PS_STRIDE + j4 * 4);
                UF2 pp;
                pp.f = make_float2(p4.x, p4.x);
                acc[r][0] = fma2(pp.u, vv[0].x, acc[r][0]);
                acc[r][1] = fma2(pp.u, vv[0].y, acc[r][1]);
                pp.f = make_float2(p4.y, p4.y);
                acc[r][0] = fma2(pp.u, vv[1].x, acc[r][0]);
                acc[r][1] = fma2(pp.u, vv[1].y, acc[r][1]);
                pp.f = make_float2(p4.z, p4.z);
                acc[r][0] = fma2(pp.u, vv[2].x, acc[r][0]);
                acc[r][1] = fma2(pp.u, vv[2].y, acc[r][1]);
                pp.f = make_float2(p4.w, p4.w);
                acc[r][0] = fma2(pp.u, vv[3].x, acc[r][0]);
                acc[r][1] = fma2(pp.u, vv[3].y, acc[r][1]);
            }
        }
        #pragma unroll
        for (int r = 0; r < 16; ++r) {
            float* dst = Rout + ((size_t)b * TT + t0 + tg * 16 + r) * (2 * DD) + 4 * d8;
            float4 o;
            o.x = ((UF2*)&acc[r][0])->f.x;  o.y = ((UF2*)&acc[r][0])->f.y;
            o.z = ((UF2*)&acc[r][1])->f.x;  o.w = ((UF2*)&acc[r][1])->f.y;
            __stcs((float4*)dst, o);
        }
    } else {
        // ------------- scatter probs into window rows (warps 4-7) ------------
        const int t2   = tid - 128;
        const int rown = t2 >> 3;           // 0..15
        const int c4   = t2 & 7;
        float* base = Aout + (size_t)b * NK * TT + t0 + 4 * c4;
        #pragma unroll
        for (int pass = 0; pass < 4; ++pass) {
            int j = pass * 16 + rown;       // 0..63 window col
            int t = 4 * c4;
            float4 v;
            v.x = Ps[(t + 0) * PS_STRIDE + j];
            v.y = Ps[(t + 1) * PS_STRIDE + j];
            v.z = Ps[(t + 2) * PS_STRIDE + j];
            v.w = Ps[(t + 3) * PS_STRIDE + j];
            __stcs((float4*)(base + (size_t)(prev + j) * TT), v);
        }
    }
}

extern "C" void kernel_launch(void* const* d_in, const int* in_sizes, int n_in,
                              void* d_out, int out_size)
{
    const float* Q  = (const float*)d_in[0];
    const float* K  = (const float*)d_in[1];
    const float* V  = (const float*)d_in[2];
    const int* prevw = (const int*)d_in[3];   // int64 or int32, sniffed in-kernel
    float* out = (float*)d_out;

    cudaFuncSetAttribute(attn_win_kernel,
                         cudaFuncAttributeMaxDynamicSharedMemorySize, SMEM_BYTES);

    dim3 grid(TT / TILE_T, BB);
    attn_win_kernel<<<grid, 256, SMEM_BYTES, 0>>>(Q, K, V, prevw, out);
}

// round 13
// speedup vs baseline: 1.4136x; 1.0007x over previous
#include <cuda_runtime.h>

// Problem constants
#define BB      16
#define TT      1024
#define NK      1024
#define DD      256
#define WIN     64
#define TILE_T  32

// Shared-memory layout (floats). 260-float row stride => 4-bank shift per row.
#define QS_STRIDE   260
#define KS_STRIDE   260
#define PS_STRIDE   68

#define QS_OFF      0
#define KS_OFF      (TILE_T * QS_STRIDE)                 // 8320
#define PS_OFF      (KS_OFF + WIN * KS_STRIDE)           // 24960
#define SMEM_FLOATS (PS_OFF + TILE_T * PS_STRIDE)        // 27136 floats
#define SMEM_BYTES  (SMEM_FLOATS * 4)                    // 108544 B -> 2 CTAs/SM

// Output layout: R (B,T,512) | alignments (B,N,T) | max_attentions (B,T)
#define R_ELEMS   ((size_t)BB * TT * (2 * DD))           // 8,388,608
#define AL_ELEMS  ((size_t)BB * NK * TT)                 // 16,777,216

typedef unsigned long long u64;
typedef unsigned int       u32;

union UF2 { u64 u; float2 f; };

// Packed fp32x2 FMA (Blackwell FFMA2) — exact fp32, 2x FFMA throughput.
__device__ __forceinline__ u64 fma2(u64 a, u64 b, u64 c) {
    u64 d;
    asm("fma.rn.f32x2 %0, %1, %2, %3;" : "=l"(d) : "l"(a), "l"(b), "l"(c));
    return d;
}

// 16-byte async global->shared copy (LDGSTS).
__device__ __forceinline__ void cp_async16(u32 smem_addr, const void* gptr) {
    asm volatile("cp.async.cg.shared.global [%0], [%1], 16;"
                 :: "r"(smem_addr), "l"(gptr));
}
__device__ __forceinline__ void cp_async_commit() {
    asm volatile("cp.async.commit_group;");
}
__device__ __forceinline__ void cp_async_wait_all() {
    asm volatile("cp.async.wait_group 0;");
}

__global__ __launch_bounds__(256, 2)
void attn_win_kernel(const float* __restrict__ Q,
                     const float* __restrict__ K,
                     const float* __restrict__ V,
                     const int*   __restrict__ prev_words,  // raw words of prev_max_attentions
                     float* __restrict__ out)
{
    extern __shared__ float smem[];
    float* Qs = smem + QS_OFF;
    float* Ks = smem + KS_OFF;   // K window during QK, then reused for V window
    float* Ps = smem + PS_OFF;

    const int tid = threadIdx.x;
    const int b   = blockIdx.y;
    const int t0  = blockIdx.x * TILE_T;

    // dtype sniff: int64 (little-endian, values < 2^31) has zero high words.
    int odd_or = prev_words[1] | prev_words[3] | prev_words[5] | prev_words[7] |
                 prev_words[9] | prev_words[11] | prev_words[13] | prev_words[15];
    const int prev = (odd_or == 0) ? prev_words[2 * b] : prev_words[b];

    float* Rout = out;                       // (B,T,512)
    float* Aout = out + R_ELEMS;             // (B,N,T), zero-filled below
    float* Mout = Aout + AL_ELEMS;           // (B,T)

    // ---------------- K window -> smem via cp.async (starts first) -----------
    {
        const char* Kg = (const char*)(K + ((size_t)b * NK + prev) * DD);
        #pragma unroll
        for (int it = 0; it < (WIN * DD / 4) / 256; ++it) {      // 16 iters
            int idx = tid + it * 256;
            int j   = idx >> 6;          // 0..63
            int d4  = idx & 63;
            u32 dst = (u32)__cvta_generic_to_shared(Ks + j * KS_STRIDE + d4 * 4);
            cp_async16(dst, Kg + (size_t)(j * 64 + d4) * 16);
        }
        cp_async_commit();
    }
    // ---------------- Q tile -> smem only (R copy deferred to QK phase) ------
    {
        const float4* Qg = (const float4*)(Q + ((size_t)b * TT + t0) * DD);
        #pragma unroll
        for (int it = 0; it < (TILE_T * DD / 4) / 256; ++it) {   // 8 iters
            int idx = tid + it * 256;
            int t   = idx >> 6;          // 0..31
            int d4  = idx & 63;          // 0..63 (float4 index)
            *(float4*)(Qs + t * QS_STRIDE + d4 * 4) = __ldg(&Qg[t * 64 + d4]);
        }
    }
    cp_async_wait_all();
    __syncthreads();

    // =================== WARP-SPECIALIZED PHASE 1 ============================
    if (tid < 128) {
        // ------------- QK^T on warps 0-3: thread tile 4 t-rows x 4 j-cols ----
        // j = jh*32 + jg + 8*jj. K loads: 8 unique rows/warp (4-bank shift ->
        // conflict-free). 8 LDS.128 feed 32 FFMA2 per iter.
        const int jg = tid & 7;
        const int tg = (tid >> 3) & 7;              // rows 4*tg .. 4*tg+3
        const int jh = tid >> 6;                    // j half: 0 or 1
        const float* qb = Qs + (size_t)(tg * 4) * QS_STRIDE;
        const float* kb = Ks + (size_t)(jh * 32 + jg) * KS_STRIDE;

        u64 acc[4][4];
        #pragma unroll
        for (int i = 0; i < 4; ++i)
            #pragma unroll
            for (int c = 0; c < 4; ++c) acc[i][c] = 0ull;

        #pragma unroll 2
        for (int d4 = 0; d4 < DD / 4; ++d4) {
            ulonglong2 k0 = *(const ulonglong2*)(kb + 0 * 8 * KS_STRIDE + d4 * 4);
            ulonglong2 k1 = *(const ulonglong2*)(kb + 1 * 8 * KS_STRIDE + d4 * 4);
            ulonglong2 k2 = *(const ulonglong2*)(kb + 2 * 8 * KS_STRIDE + d4 * 4);
            ulonglong2 k3 = *(const ulonglong2*)(kb + 3 * 8 * KS_STRIDE + d4 * 4);
            #pragma unroll
            for (int i = 0; i < 4; ++i) {
                ulonglong2 q = *(const ulonglong2*)(qb + (size_t)i * QS_STRIDE + d4 * 4);
                acc[i][0] = fma2(q.x, k0.x, acc[i][0]);
                acc[i][0] = fma2(q.y, k0.y, acc[i][0]);
                acc[i][1] = fma2(q.x, k1.x, acc[i][1]);
                acc[i][1] = fma2(q.y, k1.y, acc[i][1]);
                acc[i][2] = fma2(q.x, k2.x, acc[i][2]);
                acc[i][2] = fma2(q.y, k2.y, acc[i][2]);
                acc[i][3] = fma2(q.x, k3.x, acc[i][3]);
                acc[i][3] = fma2(q.y, k3.y, acc[i][3]);
            }
        }
        #pragma unroll
        for (int i = 0; i < 4; ++i)
            #pragma unroll
            for (int c = 0; c < 4; ++c) {
                UF2 u; u.u = acc[i][c];
                Ps[(tg * 4 + i) * PS_STRIDE + jh * 32 + jg + 8 * c] =
                    (u.f.x + u.f.y) * 0.0625f;      // * rsqrt(256)
            }
    } else {
        const int t2 = tid - 128;
        // ------------- Q -> R[:, :, 256:512] copy (warps 4-7; Q is L2-hot) ---
        {
            const float4* Qg = (const float4*)(Q + ((size_t)b * TT + t0) * DD);
            #pragma unroll
            for (int it = 0; it < (TILE_T * DD / 4) / 128; ++it) {   // 16 iters
                int idx = t2 + it * 128;
                int t   = idx >> 6;
                int d4  = idx & 63;
                __stcs((float4*)(Rout + ((size_t)b * TT + t0 + t) * (2 * DD) + DD + d4 * 4),
                       __ldg(&Qg[t * 64 + d4]));
            }
        }
        // ------------- zero-fill non-window rows of alignments ---------------
        {
            const int rown = t2 >> 3;           // 0..15
            const int c4   = t2 & 7;            // float4 col of the 32 t-cols
            float* base = Aout + (size_t)b * NK * TT + t0 + 4 * c4;
            const float4 z = make_float4(0.f, 0.f, 0.f, 0.f);
            #pragma unroll 4
            for (int pass = 0; pass < NK / 16; ++pass) {
                int n = pass * 16 + rown;
                if ((unsigned)(n - prev) >= WIN)
                    __stcs((float4*)(base + (size_t)n * TT), z);
            }
        }
    }
    __syncthreads();   // Ks (K data) dead; Ps scores complete

    // ---------------- V window -> smem (reusing Ks) via cp.async -------------
    {
        const char* Vg = (const char*)(V + ((size_t)b * NK + prev) * DD);
        #pragma unroll
        for (int it = 0; it < (WIN * DD / 4) / 256; ++it) {      // 16 iters
            int idx = tid + it * 256;
            int j   = idx >> 6;          // 0..63
            int d4  = idx & 63;
            u32 dst = (u32)__cvta_generic_to_shared(Ks + j * KS_STRIDE + d4 * 4);
            cp_async16(dst, Vg + (size_t)(j * 64 + d4) * 16);
        }
        cp_async_commit();
    }

    // ---------------- softmax + argmax: 4 rows per warp IN PARALLEL ----------
    // 8 lanes per row, 8 cols per lane. One short chain instead of 4 serial
    // row-reductions: in-lane reduce(8) -> 3 shfl stages within 8-lane group.
    {
        const int lane = tid & 31;
        const int w    = tid >> 5;            // 8 warps
        const int sub  = lane >> 3;           // 0..3 -> row within warp group
        const int li   = lane & 7;            // 0..7 -> 8-col chunk
        const int r    = w * 4 + sub;         // 0..31
        float* prow = Ps + r * PS_STRIDE + li * 8;
        float4 a = *(const float4*)(prow);
        float4 c = *(const float4*)(prow + 4);
        float v[8] = {a.x, a.y, a.z, a.w, c.x, c.y, c.z, c.w};

        float bv = v[0]; int bi = li * 8;
        #pragma unroll
        for (int t = 1; t < 8; ++t)
            if (v[t] > bv) { bv = v[t]; bi = li * 8 + t; }   // strict > = first max
        #pragma unroll
        for (int off = 1; off < 8; off <<= 1) {
            float ov = __shfl_xor_sync(0xffffffffu, bv, off);
            int   oi = __shfl_xor_sync(0xffffffffu, bi, off);
            if (ov > bv || (ov == bv && oi < bi)) { bv = ov; bi = oi; }
        }
        float e[8]; float s = 0.f;
        #pragma unroll
        for (int t = 0; t < 8; ++t) { e[t] = __expf(v[t] - bv); s += e[t]; }
        #pragma unroll
        for (int off = 1; off < 8; off <<= 1)
            s += __shfl_xor_sync(0xffffffffu, s, off);
        float inv = 1.0f / s;
        *(float4*)(prow)     = make_float4(e[0] * inv, e[1] * inv, e[2] * inv, e[3] * inv);
        *(float4*)(prow + 4) = make_float4(e[4] * inv, e[5] * inv, e[6] * inv, e[7] * inv);
        if (li == 0)
            Mout[(size_t)b * TT + t0 + r] = (float)(prev + bi);
    }
    cp_async_wait_all();
    __syncthreads();   // probs + V-in-smem visible to all

    // ---------------- scatter probs into window rows of alignments -----------
    {
        const int rown = tid >> 3;          // 0..31
        const int c4   = tid & 7;
        float* base = Aout + (size_t)b * NK * TT + t0 + 4 * c4;
        #pragma unroll
        for (int pass = 0; pass < 2; ++pass) {
            int j = pass * 32 + rown;       // 0..63 window col
            int t = 4 * c4;
            float4 v;
            v.x = Ps[(t + 0) * PS_STRIDE + j];
            v.y = Ps[(t + 1) * PS_STRIDE + j];
            v.z = Ps[(t + 2) * PS_STRIDE + j];
            v.w = Ps[(t + 3) * PS_STRIDE + j];
            __stcs((float4*)(base + (size_t)(prev + j) * TT), v);
        }
    }

    // ---------------- P @ V_window -> R[:, :, 0:256] --------------------------
    // V in smem; thread owns 8 t-rows and one float4 d-column. P loads are
    // warp-uniform (tg constant per warp) -> broadcast wavefronts.
    {
        const int d8 = tid & 63;                   // float4 index 0..63
        const int tg = tid >> 6;                   // 0..3 -> rows 8*tg..+7
        u64 acc[8][2];
        #pragma unroll
        for (int r = 0; r < 8; ++r) { acc[r][0] = 0ull; acc[r][1] = 0ull; }

        #pragma unroll 2
        for (int j4 = 0; j4 < WIN / 4; ++j4) {
            ulonglong2 vv[4];
            #pragma unroll
            for (int jj = 0; jj < 4; ++jj)
                vv[jj] = *(const ulonglong2*)(Ks + (size_t)(j4 * 4 + jj) * KS_STRIDE + d8 * 4);
            #pragma unroll
            for (int r = 0; r < 8; ++r) {
                float4 p4 = *(const float4*)(Ps + (tg * 8 + r) * PS_STRIDE + j4 * 4);
                UF2 pp;
                pp.f = make_float2(p4.x, p4.x);
                acc[r][0] = fma2(pp.u, vv[0].x, acc[r][0]);
                acc[r][1] = fma2(pp.u, vv[0].y, acc[r][1]);
                pp.f = make_float2(p4.y, p4.y);
                acc[r][0] = fma2(pp.u, vv[1].x, acc[r][0]);
                acc[r][1] = fma2(pp.u, vv[1].y, acc[r][1]);
                pp.f = make_float2(p4.z, p4.z);
                acc[r][0] = fma2(pp.u, vv[2].x, acc[r][0]);
                acc[r][1] = fma2(pp.u, vv[2].y, acc[r][1]);
                pp.f = make_float2(p4.w, p4.w);
                acc[r][0] = fma2(pp.u, vv[3].x, acc[r][0]);
                acc[r][1] = fma2(pp.u, vv[3].y, acc[r][1]);
            }
        }
        #pragma unroll
        for (int r = 0; r < 8; ++r) {
            float* dst = Rout + ((size_t)b * TT + t0 + tg * 8 + r) * (2 * DD) + 4 * d8;
            float4 o;
            o.x = ((UF2*)&acc[r][0])->f.x;  o.y = ((UF2*)&acc[r][0])->f.y;
            o.z = ((UF2*)&acc[r][1])->f.x;  o.w = ((UF2*)&acc[r][1])->f.y;
            __stcs((float4*)dst, o);
        }
    }
}

extern "C" void kernel_launch(void* const* d_in, const int* in_sizes, int n_in,
                              void* d_out, int out_size)
{
    const float* Q  = (const float*)d_in[0];
    const float* K  = (const float*)d_in[1];
    const float* V  = (const float*)d_in[2];
    const int* prevw = (const int*)d_in[3];   // int64 or int32, sniffed in-kernel
    float* out = (float*)d_out;

    cudaFuncSetAttribute(attn_win_kernel,
                         cudaFuncAttributeMaxDynamicSharedMemorySize, SMEM_BYTES);

    dim3 grid(TT / TILE_T, BB);
    attn_win_kernel<<<grid, 256, SMEM_BYTES, 0>>>(Q, K, V, prevw, out);
}

// round 15
// speedup vs baseline: 1.4597x; 1.0326x over previous
#include <cuda_runtime.h>

// Problem constants
#define BB      16
#define TT      1024
#define NK      1024
#define DD      256
#define WIN     64

// Each CTA handles 64 t-rows (two 32-row tiles A/B) against ONE K/V window.
// Shared memory (floats):
//   Qs: 32 x 260 pad-stride                                 8320
//   Ks: 64 x 256 XOR-swizzled (K window, then V window)    16384
//   Ps: 64 x 64  (probs: rows 0-31 tile A, 32-63 tile B)    4096
// Total 28800 floats = 115200 B -> 2 CTAs/SM (2*(115200+1024) <= 233472).
//
// K/V swizzle: 16B chunk d4 of row j lives at chunk (d4 ^ (j & 7)).
// QK reads rows jh*32+jg at uniform d4 -> 8 chunks with distinct low-3 bits
// -> all 32 banks, conflict-free. AV reads a full row -> permutation of all
// 64 chunks -> conflict-free.
#define QS_STRIDE   260
#define KS_STRIDE   256
#define PS_STRIDE   64

#define QS_OFF      0
#define KS_OFF      8320
#define PS_OFF      (KS_OFF + WIN * KS_STRIDE)           // 24704
#define SMEM_FLOATS (PS_OFF + 64 * PS_STRIDE)            // 28800
#define SMEM_BYTES  (SMEM_FLOATS * 4)                    // 115200

// Output layout: R (B,T,512) | alignments (B,N,T) | max_attentions (B,T)
#define R_ELEMS   ((size_t)BB * TT * (2 * DD))           // 8,388,608
#define AL_ELEMS  ((size_t)BB * NK * TT)                 // 16,777,216

typedef unsigned long long u64;
typedef unsigned int       u32;

union UF2 { u64 u; float2 f; };

// Packed fp32x2 FMA (Blackwell FFMA2) — exact fp32, 2x FFMA throughput.
__device__ __forceinline__ u64 fma2(u64 a, u64 b, u64 c) {
    u64 d;
    asm("fma.rn.f32x2 %0, %1, %2, %3;" : "=l"(d) : "l"(a), "l"(b), "l"(c));
    return d;
}

// 16-byte async global->shared copy (LDGSTS).
__device__ __forceinline__ void cp_async16(u32 smem_addr, const void* gptr) {
    asm volatile("cp.async.cg.shared.global [%0], [%1], 16;"
                 :: "r"(smem_addr), "l"(gptr));
}
__device__ __forceinline__ void cp_async_commit() {
    asm volatile("cp.async.commit_group;");
}
__device__ __forceinline__ void cp_async_wait_all() {
    asm volatile("cp.async.wait_group 0;");
}

// ---- QK^T for one 32-row tile (called by tid<128). 4 t-rows x 4 j-cols per
// thread; K rows swizzled (see above) -> conflict-free.
__device__ __forceinline__ void qk_half(const float* __restrict__ Qs,
                                        const float* __restrict__ Ks,
                                        float* __restrict__ Pdst, int tid)
{
    const int jg = tid & 7;
    const int tg = (tid >> 3) & 7;              // rows 4*tg .. 4*tg+3
    const int jh = tid >> 6;                    // j half: 0 or 1
    const float* qb = Qs + (size_t)(tg * 4) * QS_STRIDE;
    // K rows jh*32+jg+8m, m=0..3: (row & 7) == jg for all m -> same swizzle.
    const float* kb = Ks + (size_t)(jh * 32 + jg) * KS_STRIDE;
    const int sw = jg;                          // chunk XOR for these rows

    u64 acc[4][4];
    #pragma unroll
    for (int i = 0; i < 4; ++i)
        #pragma unroll
        for (int c = 0; c < 4; ++c) acc[i][c] = 0ull;

    #pragma unroll 2
    for (int d4 = 0; d4 < DD / 4; ++d4) {
        const int ko = (d4 ^ sw) * 4;           // swizzled float offset
        ulonglong2 k0 = *(const ulonglong2*)(kb + 0 * 8 * KS_STRIDE + ko);
        ulonglong2 k1 = *(const ulonglong2*)(kb + 1 * 8 * KS_STRIDE + ko);
        ulonglong2 k2 = *(const ulonglong2*)(kb + 2 * 8 * KS_STRIDE + ko);
        ulonglong2 k3 = *(const ulonglong2*)(kb + 3 * 8 * KS_STRIDE + ko);
        #pragma unroll
        for (int i = 0; i < 4; ++i) {
            ulonglong2 q = *(const ulonglong2*)(qb + (size_t)i * QS_STRIDE + d4 * 4);
            acc[i][0] = fma2(q.x, k0.x, acc[i][0]);
            acc[i][0] = fma2(q.y, k0.y, acc[i][0]);
            acc[i][1] = fma2(q.x, k1.x, acc[i][1]);
            acc[i][1] = fma2(q.y, k1.y, acc[i][1]);
            acc[i][2] = fma2(q.x, k2.x, acc[i][2]);
            acc[i][2] = fma2(q.y, k2.y, acc[i][2]);
            acc[i][3] = fma2(q.x, k3.x, acc[i][3]);
            acc[i][3] = fma2(q.y, k3.y, acc[i][3]);
        }
    }
    #pragma unroll
    for (int i = 0; i < 4; ++i)
        #pragma unroll
        for (int c = 0; c < 4; ++c) {
            UF2 u; u.u = acc[i][c];
            Pdst[(tg * 4 + i) * PS_STRIDE + jh * 32 + jg + 8 * c] =
                (u.f.x + u.f.y) * 0.0625f;      // * rsqrt(256)
        }
}

// ---- softmax + argmax over one 32-row tile (all 256 threads; 8 warps x 4
// rows in parallel, 8 lanes per row).
__device__ __forceinline__ void softmax_half(float* __restrict__ Pbase,
                                             float* __restrict__ Mdst,
                                             int tid, int prev)
{
    const int lane = tid & 31;
    const int w    = tid >> 5;            // 8 warps
    const int sub  = lane >> 3;           // row within warp group
    const int li   = lane & 7;            // 8-col chunk
    const int r    = w * 4 + sub;         // 0..31
    float* prow = Pbase + r * PS_STRIDE + li * 8;
    float4 a = *(const float4*)(prow);
    float4 c = *(const float4*)(prow + 4);
    float v[8] = {a.x, a.y, a.z, a.w, c.x, c.y, c.z, c.w};

    float bv = v[0]; int bi = li * 8;
    #pragma unroll
    for (int t = 1; t < 8; ++t)
        if (v[t] > bv) { bv = v[t]; bi = li * 8 + t; }   // strict > = first max
    #pragma unroll
    for (int off = 1; off < 8; off <<= 1) {
        float ov = __shfl_xor_sync(0xffffffffu, bv, off);
        int   oi = __shfl_xor_sync(0xffffffffu, bi, off);
        if (ov > bv || (ov == bv && oi < bi)) { bv = ov; bi = oi; }
    }
    float e[8]; float s = 0.f;
    #pragma unroll
    for (int t = 0; t < 8; ++t) { e[t] = __expf(v[t] - bv); s += e[t]; }
    #pragma unroll
    for (int off = 1; off < 8; off <<= 1)
        s += __shfl_xor_sync(0xffffffffu, s, off);
    float inv = 1.0f / s;
    *(float4*)(prow)     = make_float4(e[0] * inv, e[1] * inv, e[2] * inv, e[3] * inv);
    *(float4*)(prow + 4) = make_float4(e[4] * inv, e[5] * inv, e[6] * inv, e[7] * inv);
    if (li == 0)
        Mdst[r] = (float)(prev + bi);
}

__global__ __launch_bounds__(256, 2)
void attn_win_kernel(const float* __restrict__ Q,
                     const float* __restrict__ K,
                     const float* __restrict__ V,
                     const int*   __restrict__ prev_words,
                     float* __restrict__ out)
{
    extern __shared__ float smem[];
    float* Qs = smem + QS_OFF;
    float* Ks = smem + KS_OFF;   // K window during QK, then reused for V window
    float* Ps = smem + PS_OFF;

    const int tid = threadIdx.x;
    const int b   = blockIdx.y;
    const int t0  = blockIdx.x * 64;         // this CTA: t-rows t0 .. t0+63

    // dtype sniff: int64 (little-endian, values < 2^31) has zero high words.
    int odd_or = prev_words[1] | prev_words[3] | prev_words[5] | prev_words[7] |
                 prev_words[9] | prev_words[11] | prev_words[13] | prev_words[15];
    const int prev = (odd_or == 0) ? prev_words[2 * b] : prev_words[b];

    float* Rout = out;                       // (B,T,512)
    float* Aout = out + R_ELEMS;             // (B,N,T)
    float* Mout = Aout + AL_ELEMS;           // (B,T)

    // ---------------- K window -> smem (swizzled) via cp.async ---------------
    {
        const char* Kg = (const char*)(K + ((size_t)b * NK + prev) * DD);
        #pragma unroll
        for (int it = 0; it < 16; ++it) {
            int idx = tid + it * 256;
            int j   = idx >> 6;
            int d4  = idx & 63;
            u32 dst = (u32)__cvta_generic_to_shared(
                Ks + j * KS_STRIDE + (d4 ^ (j & 7)) * 4);
            cp_async16(dst, Kg + (size_t)(j * 64 + d4) * 16);
        }
        cp_async_commit();
    }
    // ---------------- Q tile A -> smem ---------------------------------------
    {
        const float4* Qg = (const float4*)(Q + ((size_t)b * TT + t0) * DD);
        #pragma unroll
        for (int it = 0; it < 8; ++it) {
            int idx = tid + it * 256;
            int t   = idx >> 6;
            int d4  = idx & 63;
            *(float4*)(Qs + t * QS_STRIDE + d4 * 4) = __ldg(&Qg[t * 64 + d4]);
        }
    }
    cp_async_wait_all();
    __syncthreads();

    // ===== P1: QK_A  ||  Q_A->R copy + alignments zero-fill ==================
    if (tid < 128) {
        qk_half(Qs, Ks, Ps, tid);
    } else {
        const int t2 = tid - 128;
        {   // Q_A -> R[:, :, 256:512] (Q is L2-hot)
            const float4* Qg = (const float4*)(Q + ((size_t)b * TT + t0) * DD);
            #pragma unroll
            for (int it = 0; it < 16; ++it) {
                int idx = t2 + it * 128;
                int t   = idx >> 6;
                int d4  = idx & 63;
                __stcs((float4*)(Rout + ((size_t)b * TT + t0 + t) * (2 * DD) + DD + d4 * 4),
                       __ldg(&Qg[t * 64 + d4]));
            }
        }
        {   // zero-fill non-window rows for this CTA's 64 t-cols
            const int c16  = t2 & 15;           // float4 col 0..15
            const int rown = t2 >> 4;           // 0..7
            float* base = Aout + (size_t)b * NK * TT + t0 + 4 * c16;
            const float4 z = make_float4(0.f, 0.f, 0.f, 0.f);
            #pragma unroll 4
            for (int pass = 0; pass < NK / 8; ++pass) {
                int n = pass * 8 + rown;
                if ((unsigned)(n - prev) >= WIN)
                    __stcs((float4*)(base + (size_t)n * TT), z);
            }
        }
    }
    __syncthreads();

    // ===== P2: stage Q tile B + softmax_A ====================================
    {
        const float4* Qg = (const float4*)(Q + ((size_t)b * TT + t0 + 32) * DD);
        #pragma unroll
        for (int it = 0; it < 8; ++it) {
            int idx = tid + it * 256;
            int t   = idx >> 6;
            int d4  = idx & 63;
            *(float4*)(Qs + t * QS_STRIDE + d4 * 4) = __ldg(&Qg[t * 64 + d4]);
        }
    }
    softmax_half(Ps, Mout + (size_t)b * TT + t0, tid, prev);
    __syncthreads();

    // ===== P3: QK_B  ||  Q_B->R copy + scatter_A =============================
    if (tid < 128) {
        qk_half(Qs, Ks, Ps + 32 * PS_STRIDE, tid);
    } else {
        const int t2 = tid - 128;
        {   // Q_B -> R copy
            const float4* Qg = (const float4*)(Q + ((size_t)b * TT + t0 + 32) * DD);
            #pragma unroll
            for (int it = 0; it < 16; ++it) {
                int idx = t2 + it * 128;
                int t   = idx >> 6;
                int d4  = idx & 63;
                __stcs((float4*)(Rout + ((size_t)b * TT + t0 + 32 + t) * (2 * DD) + DD + d4 * 4),
                       __ldg(&Qg[t * 64 + d4]));
            }
        }
        {   // scatter tile-A probs into window rows (t-cols t0..t0+31)
            #pragma unroll
            for (int it = 0; it < 4; ++it) {
                int item = t2 + it * 128;       // 0..511
                int j    = item >> 3;           // 0..63
                int c4   = item & 7;            // float4 col 0..7
                float4 v;
                v.x = Ps[(4 * c4 + 0) * PS_STRIDE + j];
                v.y = Ps[(4 * c4 + 1) * PS_STRIDE + j];
                v.z = Ps[(4 * c4 + 2) * PS_STRIDE + j];
                v.w = Ps[(4 * c4 + 3) * PS_STRIDE + j];
                __stcs((float4*)(Aout + ((size_t)b * NK + prev + j) * TT + t0 + 4 * c4), v);
            }
        }
    }
    __syncthreads();

    // ===== P4: V window -> smem (reusing Ks, swizzled) + softmax_B ===========
    {
        const char* Vg = (const char*)(V + ((size_t)b * NK + prev) * DD);
        #pragma unroll
        for (int it = 0; it < 16; ++it) {
            int idx = tid + it * 256;
            int j   = idx >> 6;
            int d4  = idx & 63;
            u32 dst = (u32)__cvta_generic_to_shared(
                Ks + j * KS_STRIDE + (d4 ^ (j & 7)) * 4);
            cp_async16(dst, Vg + (size_t)(j * 64 + d4) * 16);
        }
        cp_async_commit();
    }
    softmax_half(Ps + 32 * PS_STRIDE, Mout + (size_t)b * TT + t0 + 32, tid, prev);
    cp_async_wait_all();
    __syncthreads();

    // ===== P5: scatter_B + AV for both tiles =================================
    {   // scatter tile-B probs (t-cols t0+32..t0+63), 2 items/thread
        #pragma unroll
        for (int it = 0; it < 2; ++it) {
            int item = tid + it * 256;          // 0..511
            int j    = item >> 3;
            int c4   = item & 7;
            float4 v;
            v.x = Ps[(32 + 4 * c4 + 0) * PS_STRIDE + j];
            v.y = Ps[(32 + 4 * c4 + 1) * PS_STRIDE + j];
            v.z = Ps[(32 + 4 * c4 + 2) * PS_STRIDE + j];
            v.w = Ps[(32 + 4 * c4 + 3) * PS_STRIDE + j];
            __stcs((float4*)(Aout + ((size_t)b * NK + prev + j) * TT + t0 + 32 + 4 * c4), v);
        }
    }
    {   // AV: thread owns 8 t-rows x one float4 d-col; run tile A then tile B.
        const int d8 = tid & 63;
        const int tg = tid >> 6;                // 0..3 -> rows 8*tg..+7
        #pragma unroll 1
        for (int h = 0; h < 2; ++h) {
            const float* Pb = Ps + (h * 32 + tg * 8) * PS_STRIDE;
            u64 acc[8][2];
            #pragma unroll
            for (int r = 0; r < 8; ++r) { acc[r][0] = 0ull; acc[r][1] = 0ull; }

            #pragma unroll 2
            for (int j4 = 0; j4 < WIN / 4; ++j4) {
                ulonglong2 vv[4];
                #pragma unroll
                for (int jj = 0; jj < 4; ++jj) {
                    int row = j4 * 4 + jj;
                    vv[jj] = *(const ulonglong2*)(
                        Ks + (size_t)row * KS_STRIDE + (d8 ^ (row & 7)) * 4);
                }
                #pragma unroll
                for (int r = 0; r < 8; ++r) {
                    float4 p4 = *(const float4*)(Pb + r * PS_STRIDE + j4 * 4);
                    UF2 pp;
                    pp.f = make_float2(p4.x, p4.x);
                    acc[r][0] = fma2(pp.u, vv[0].x, acc[r][0]);
                    acc[r][1] = fma2(pp.u, vv[0].y, acc[r][1]);
                    pp.f = make_float2(p4.y, p4.y);
                    acc[r][0] = fma2(pp.u, vv[1].x, acc[r][0]);
                    acc[r][1] = fma2(pp.u, vv[1].y, acc[r][1]);
                    pp.f = make_float2(p4.z, p4.z);
                    acc[r][0] = fma2(pp.u, vv[2].x, acc[r][0]);
                    acc[r][1] = fma2(pp.u, vv[2].y, acc[r][1]);
                    pp.f = make_float2(p4.w, p4.w);
                    acc[r][0] = fma2(pp.u, vv[3].x, acc[r][0]);
                    acc[r][1] = fma2(pp.u, vv[3].y, acc[r][1]);
                }
            }
            #pragma unroll
            for (int r = 0; r < 8; ++r) {
                float* dst = Rout + ((size_t)b * TT + t0 + h * 32 + tg * 8 + r) * (2 * DD) + 4 * d8;
                float4 o;
                o.x = ((UF2*)&acc[r][0])->f.x;  o.y = ((UF2*)&acc[r][0])->f.y;
                o.z = ((UF2*)&acc[r][1])->f.x;  o.w = ((UF2*)&acc[r][1])->f.y;
                __stcs((float4*)dst, o);
            }
        }
    }
}

extern "C" void kernel_launch(void* const* d_in, const int* in_sizes, int n_in,
                              void* d_out, int out_size)
{
    const float* Q  = (const float*)d_in[0];
    const float* K  = (const float*)d_in[1];
    const float* V  = (const float*)d_in[2];
    const int* prevw = (const int*)d_in[3];   // int64 or int32, sniffed in-kernel
    float* out = (float*)d_out;

    cudaFuncSetAttribute(attn_win_kernel,
                         cudaFuncAttributeMaxDynamicSharedMemorySize, SMEM_BYTES);

    dim3 grid(TT / 64, BB);                   // 256 CTAs -> single wave at occ 2
    attn_win_kernel<<<grid, 256, SMEM_BYTES, 0>>>(Q, K, V, prevw, out);
}

// round 16
// speedup vs baseline: 1.5467x; 1.0596x over previous
#include <cuda_runtime.h>

// Problem constants
#define BB      16
#define TT      1024
#define NK      1024
#define DD      256
#define WIN     64

// Each CTA handles 64 t-rows (two 32-row tiles A/B) against ONE K/V window.
// Shared memory (floats):
//   Qs: 32 x 260 pad-stride                                 8320
//   Ks: 64 x 256 XOR-swizzled (K window, then V window)    16384
//   Ps: 64 x 64  (probs: rows 0-31 tile A, 32-63 tile B)    4096
// Total 28800 floats = 115200 B -> 2 CTAs/SM.
//
// K/V swizzle: 16B chunk d4 of row j lives at chunk (d4 ^ (j & 7)).
#define QS_STRIDE   260
#define KS_STRIDE   256
#define PS_STRIDE   64

#define QS_OFF      0
#define KS_OFF      8320
#define PS_OFF      (KS_OFF + WIN * KS_STRIDE)           // 24704
#define SMEM_FLOATS (PS_OFF + 64 * PS_STRIDE)            // 28800
#define SMEM_BYTES  (SMEM_FLOATS * 4)                    // 115200

// Output layout: R (B,T,512) | alignments (B,N,T) | max_attentions (B,T)
#define R_ELEMS   ((size_t)BB * TT * (2 * DD))           // 8,388,608
#define AL_ELEMS  ((size_t)BB * NK * TT)                 // 16,777,216

typedef unsigned long long u64;
typedef unsigned int       u32;

union UF2 { u64 u; float2 f; };

// Packed fp32x2 FMA (Blackwell FFMA2) — exact fp32, 2x FFMA throughput.
__device__ __forceinline__ u64 fma2(u64 a, u64 b, u64 c) {
    u64 d;
    asm("fma.rn.f32x2 %0, %1, %2, %3;" : "=l"(d) : "l"(a), "l"(b), "l"(c));
    return d;
}

// 16-byte async global->shared copy (LDGSTS).
__device__ __forceinline__ void cp_async16(u32 smem_addr, const void* gptr) {
    asm volatile("cp.async.cg.shared.global [%0], [%1], 16;"
                 :: "r"(smem_addr), "l"(gptr));
}
__device__ __forceinline__ void cp_async_commit() {
    asm volatile("cp.async.commit_group;");
}
__device__ __forceinline__ void cp_async_wait_all() {
    asm volatile("cp.async.wait_group 0;");
}

// ---- QK^T for one 32-row tile (called by tid<128). 4 t-rows x 4 j-cols per
// thread; K rows swizzled -> conflict-free.
__device__ __forceinline__ void qk_half(const float* __restrict__ Qs,
                                        const float* __restrict__ Ks,
                                        float* __restrict__ Pdst, int tid)
{
    const int jg = tid & 7;
    const int tg = (tid >> 3) & 7;              // rows 4*tg .. 4*tg+3
    const int jh = tid >> 6;                    // j half: 0 or 1
    const float* qb = Qs + (size_t)(tg * 4) * QS_STRIDE;
    // K rows jh*32+jg+8m: (row & 7) == jg for all m -> same swizzle.
    const float* kb = Ks + (size_t)(jh * 32 + jg) * KS_STRIDE;
    const int sw = jg;

    u64 acc[4][4];
    #pragma unroll
    for (int i = 0; i < 4; ++i)
        #pragma unroll
        for (int c = 0; c < 4; ++c) acc[i][c] = 0ull;

    #pragma unroll 2
    for (int d4 = 0; d4 < DD / 4; ++d4) {
        const int ko = (d4 ^ sw) * 4;           // swizzled float offset
        ulonglong2 k0 = *(const ulonglong2*)(kb + 0 * 8 * KS_STRIDE + ko);
        ulonglong2 k1 = *(const ulonglong2*)(kb + 1 * 8 * KS_STRIDE + ko);
        ulonglong2 k2 = *(const ulonglong2*)(kb + 2 * 8 * KS_STRIDE + ko);
        ulonglong2 k3 = *(const ulonglong2*)(kb + 3 * 8 * KS_STRIDE + ko);
        #pragma unroll
        for (int i = 0; i < 4; ++i) {
            ulonglong2 q = *(const ulonglong2*)(qb + (size_t)i * QS_STRIDE + d4 * 4);
            acc[i][0] = fma2(q.x, k0.x, acc[i][0]);
            acc[i][0] = fma2(q.y, k0.y, acc[i][0]);
            acc[i][1] = fma2(q.x, k1.x, acc[i][1]);
            acc[i][1] = fma2(q.y, k1.y, acc[i][1]);
            acc[i][2] = fma2(q.x, k2.x, acc[i][2]);
            acc[i][2] = fma2(q.y, k2.y, acc[i][2]);
            acc[i][3] = fma2(q.x, k3.x, acc[i][3]);
            acc[i][3] = fma2(q.y, k3.y, acc[i][3]);
        }
    }
    #pragma unroll
    for (int i = 0; i < 4; ++i)
        #pragma unroll
        for (int c = 0; c < 4; ++c) {
            UF2 u; u.u = acc[i][c];
            Pdst[(tg * 4 + i) * PS_STRIDE + jh * 32 + jg + 8 * c] =
                (u.f.x + u.f.y) * 0.0625f;      // * rsqrt(256)
        }
}

// ---- softmax + argmax over one 32-row tile (all 256 threads; 8 warps x 4
// rows in parallel, 8 lanes per row).
__device__ __forceinline__ void softmax_half(float* __restrict__ Pbase,
                                             float* __restrict__ Mdst,
                                             int tid, int prev)
{
    const int lane = tid & 31;
    const int w    = tid >> 5;            // 8 warps
    const int sub  = lane >> 3;           // row within warp group
    const int li   = lane & 7;            // 8-col chunk
    const int r    = w * 4 + sub;         // 0..31
    float* prow = Pbase + r * PS_STRIDE + li * 8;
    float4 a = *(const float4*)(prow);
    float4 c = *(const float4*)(prow + 4);
    float v[8] = {a.x, a.y, a.z, a.w, c.x, c.y, c.z, c.w};

    float bv = v[0]; int bi = li * 8;
    #pragma unroll
    for (int t = 1; t < 8; ++t)
        if (v[t] > bv) { bv = v[t]; bi = li * 8 + t; }   // strict > = first max
    #pragma unroll
    for (int off = 1; off < 8; off <<= 1) {
        float ov = __shfl_xor_sync(0xffffffffu, bv, off);
        int   oi = __shfl_xor_sync(0xffffffffu, bi, off);
        if (ov > bv || (ov == bv && oi < bi)) { bv = ov; bi = oi; }
    }
    float e[8]; float s = 0.f;
    #pragma unroll
    for (int t = 0; t < 8; ++t) { e[t] = __expf(v[t] - bv); s += e[t]; }
    #pragma unroll
    for (int off = 1; off < 8; off <<= 1)
        s += __shfl_xor_sync(0xffffffffu, s, off);
    float inv = 1.0f / s;
    *(float4*)(prow)     = make_float4(e[0] * inv, e[1] * inv, e[2] * inv, e[3] * inv);
    *(float4*)(prow + 4) = make_float4(e[4] * inv, e[5] * inv, e[6] * inv, e[7] * inv);
    if (li == 0)
        Mdst[r] = (float)(prev + bi);
}

__global__ __launch_bounds__(256, 2)
void attn_win_kernel(const float* __restrict__ Q,
                     const float* __restrict__ K,
                     const float* __restrict__ V,
                     const int*   __restrict__ prev_words,
                     float* __restrict__ out)
{
    extern __shared__ float smem[];
    float* Qs = smem + QS_OFF;
    float* Ks = smem + KS_OFF;   // K window during QK, then reused for V window
    float* Ps = smem + PS_OFF;

    const int tid = threadIdx.x;
    const int b   = blockIdx.y;
    const int t0  = blockIdx.x * 64;         // this CTA: t-rows t0 .. t0+63

    // dtype sniff: int64 (little-endian, values < 2^31) has zero high words.
    int odd_or = prev_words[1] | prev_words[3] | prev_words[5] | prev_words[7] |
                 prev_words[9] | prev_words[11] | prev_words[13] | prev_words[15];
    const int prev = (odd_or == 0) ? prev_words[2 * b] : prev_words[b];

    float* Rout = out;                       // (B,T,512)
    float* Aout = out + R_ELEMS;             // (B,N,T)
    float* Mout = Aout + AL_ELEMS;           // (B,T)

    // ===== P0: K window -> smem (swizzled) + Q_A stage (+R write) ============
    {
        const char* Kg = (const char*)(K + ((size_t)b * NK + prev) * DD);
        #pragma unroll
        for (int it = 0; it < 16; ++it) {
            int idx = tid + it * 256;
            int j   = idx >> 6;
            int d4  = idx & 63;
            u32 dst = (u32)__cvta_generic_to_shared(
                Ks + j * KS_STRIDE + (d4 ^ (j & 7)) * 4);
            cp_async16(dst, Kg + (size_t)(j * 64 + d4) * 16);
        }
        cp_async_commit();
    }
    {
        const float4* Qg = (const float4*)(Q + ((size_t)b * TT + t0) * DD);
        #pragma unroll
        for (int it = 0; it < 8; ++it) {
            int idx = tid + it * 256;
            int t   = idx >> 6;
            int d4  = idx & 63;
            float4 q4 = __ldg(&Qg[t * 64 + d4]);
            *(float4*)(Qs + t * QS_STRIDE + d4 * 4) = q4;
            __stcs((float4*)(Rout + ((size_t)b * TT + t0 + t) * (2 * DD) + DD + d4 * 4), q4);
        }
    }
    cp_async_wait_all();
    __syncthreads();                         // barrier 1

    // ===== P1: QK_A  ||  zero-fill first half ================================
    if (tid < 128) {
        qk_half(Qs, Ks, Ps, tid);
    } else {
        const int t2   = tid - 128;
        const int c16  = t2 & 15;            // float4 col 0..15
        const int rown = t2 >> 4;            // 0..7
        float* base = Aout + (size_t)b * NK * TT + t0 + 4 * c16;
        const float4 z = make_float4(0.f, 0.f, 0.f, 0.f);
        #pragma unroll 4
        for (int pass = 0; pass < 64; ++pass) {
            int n = pass * 8 + rown;         // n 0..511
            if ((unsigned)(n - prev) >= WIN)
                __stcs((float4*)(base + (size_t)n * TT), z);
        }
    }
    __syncthreads();                         // barrier 2

    // ===== P2: Q_B stage (+R write), all threads =============================
    {
        const float4* Qg = (const float4*)(Q + ((size_t)b * TT + t0 + 32) * DD);
        #pragma unroll
        for (int it = 0; it < 8; ++it) {
            int idx = tid + it * 256;
            int t   = idx >> 6;
            int d4  = idx & 63;
            float4 q4 = __ldg(&Qg[t * 64 + d4]);
            *(float4*)(Qs + t * QS_STRIDE + d4 * 4) = q4;
            __stcs((float4*)(Rout + ((size_t)b * TT + t0 + 32 + t) * (2 * DD) + DD + d4 * 4), q4);
        }
    }
    __syncthreads();                         // barrier 3

    // ===== P3: QK_B  ||  zero-fill second half ===============================
    if (tid < 128) {
        qk_half(Qs, Ks, Ps + 32 * PS_STRIDE, tid);
    } else {
        const int t2   = tid - 128;
        const int c16  = t2 & 15;
        const int rown = t2 >> 4;
        float* base = Aout + (size_t)b * NK * TT + t0 + 4 * c16;
        const float4 z = make_float4(0.f, 0.f, 0.f, 0.f);
        #pragma unroll 4
        for (int pass = 64; pass < 128; ++pass) {
            int n = pass * 8 + rown;         // n 512..1023
            if ((unsigned)(n - prev) >= WIN)
                __stcs((float4*)(base + (size_t)n * TT), z);
        }
    }
    __syncthreads();                         // barrier 4 (K dead)

    // ===== P4: V window -> smem (swizzled) + softmax A & B ===================
    {
        const char* Vg = (const char*)(V + ((size_t)b * NK + prev) * DD);
        #pragma unroll
        for (int it = 0; it < 16; ++it) {
            int idx = tid + it * 256;
            int j   = idx >> 6;
            int d4  = idx & 63;
            u32 dst = (u32)__cvta_generic_to_shared(
                Ks + j * KS_STRIDE + (d4 ^ (j & 7)) * 4);
            cp_async16(dst, Vg + (size_t)(j * 64 + d4) * 16);
        }
        cp_async_commit();
    }
    softmax_half(Ps,                  Mout + (size_t)b * TT + t0,      tid, prev);
    softmax_half(Ps + 32 * PS_STRIDE, Mout + (size_t)b * TT + t0 + 32, tid, prev);
    cp_async_wait_all();
    __syncthreads();                         // barrier 5 (probs + V visible)

    // ===== P5: scatter A+B + AV both tiles ===================================
    {   // scatter: 64 j-rows x 16 float4 t-cols = 1024 items, 4/thread
        #pragma unroll
        for (int it = 0; it < 4; ++it) {
            int item = tid + it * 256;
            int j    = item >> 4;            // 0..63
            int c16  = item & 15;            // float4 col 0..15 (64 t-cols)
            float4 v;
            v.x = Ps[(4 * c16 + 0) * PS_STRIDE + j];
            v.y = Ps[(4 * c16 + 1) * PS_STRIDE + j];
            v.z = Ps[(4 * c16 + 2) * PS_STRIDE + j];
            v.w = Ps[(4 * c16 + 3) * PS_STRIDE + j];
            __stcs((float4*)(Aout + ((size_t)b * NK + prev + j) * TT + t0 + 4 * c16), v);
        }
    }
    {   // AV: thread owns 8 t-rows x one float4 d-col; tile A then tile B.
        const int d8 = tid & 63;
        const int tg = tid >> 6;             // 0..3 -> rows 8*tg..+7
        #pragma unroll 1
        for (int h = 0; h < 2; ++h) {
            const float* Pb = Ps + (h * 32 + tg * 8) * PS_STRIDE;
            u64 acc[8][2];
            #pragma unroll
            for (int r = 0; r < 8; ++r) { acc[r][0] = 0ull; acc[r][1] = 0ull; }

            #pragma unroll 2
            for (int j4 = 0; j4 < WIN / 4; ++j4) {
                ulonglong2 vv[4];
                #pragma unroll
                for (int jj = 0; jj < 4; ++jj) {
                    int row = j4 * 4 + jj;
                    vv[jj] = *(const ulonglong2*)(
                        Ks + (size_t)row * KS_STRIDE + (d8 ^ (row & 7)) * 4);
                }
                #pragma unroll
                for (int r = 0; r < 8; ++r) {
                    float4 p4 = *(const float4*)(Pb + r * PS_STRIDE + j4 * 4);
                    UF2 pp;
                    pp.f = make_float2(p4.x, p4.x);
                    acc[r][0] = fma2(pp.u, vv[0].x, acc[r][0]);
                    acc[r][1] = fma2(pp.u, vv[0].y, acc[r][1]);
                    pp.f = make_float2(p4.y, p4.y);
                    acc[r][0] = fma2(pp.u, vv[1].x, acc[r][0]);
                    acc[r][1] = fma2(pp.u, vv[1].y, acc[r][1]);
                    pp.f = make_float2(p4.z, p4.z);
                    acc[r][0] = fma2(pp.u, vv[2].x, acc[r][0]);
                    acc[r][1] = fma2(pp.u, vv[2].y, acc[r][1]);
                    pp.f = make_float2(p4.w, p4.w);
                    acc[r][0] = fma2(pp.u, vv[3].x, acc[r][0]);
                    acc[r][1] = fma2(pp.u, vv[3].y, acc[r][1]);
                }
            }
            #pragma unroll
            for (int r = 0; r < 8; ++r) {
                float* dst = Rout + ((size_t)b * TT + t0 + h * 32 + tg * 8 + r) * (2 * DD) + 4 * d8;
                float4 o;
                o.x = ((UF2*)&acc[r][0])->f.x;  o.y = ((UF2*)&acc[r][0])->f.y;
                o.z = ((UF2*)&acc[r][1])->f.x;  o.w = ((UF2*)&acc[r][1])->f.y;
                __stcs((float4*)dst, o);
            }
        }
    }
}

extern "C" void kernel_launch(void* const* d_in, const int* in_sizes, int n_in,
                              void* d_out, int out_size)
{
    const float* Q  = (const float*)d_in[0];
    const float* K  = (const float*)d_in[1];
    const float* V  = (const float*)d_in[2];
    const int* prevw = (const int*)d_in[3];   // int64 or int32, sniffed in-kernel
    float* out = (float*)d_out;

    cudaFuncSetAttribute(attn_win_kernel,
                         cudaFuncAttributeMaxDynamicSharedMemorySize, SMEM_BYTES);

    dim3 grid(TT / 64, BB);                   // 256 CTAs -> single wave at occ 2
    attn_win_kernel<<<grid, 256, SMEM_BYTES, 0>>>(Q, K, V, prevw, out);
}